// round 2
// baseline (speedup 1.0000x reference)
#include <cuda_runtime.h>
#include <math.h>

#define H_IN 321
#define W_IN 321
#define HS 41
#define WS 41
#define NPIX 1681
#define NCH 21
#define CP 24
#define NBATCH 16
#define NITERS 10

#define INVSC (321.0f/41.0f)
#define AG 8.0f                 /* 1/(2*(3/12)^2) */
#define ABF 0.011250f           /* 1/(2*(80/12)^2) */
#define BBF (1.0f/338.0f)       /* 1/(2*13^2) */
#define CG 3.0f
#define CB 10.0f
#define EPSV 1e-5f

// ---------------- static device buffers (no allocs allowed) ----------------
static __device__ float g_colors[NBATCH*NPIX*4];          // rgb + pad
static __device__ float g_eg[81*81];                      // spatial gaussian table
static __device__ float g_rsg[NPIX];                      // 1/sqrt(row sum) gaussian
static __device__ float g_rsb[NBATCH*NPIX];               // 1/sqrt(row sum) bilateral
static __device__ float g_probs[NBATCH*NPIX*CP];
static __device__ float g_logu[NBATCH*NPIX*CP];
static __device__ float g_Qa[NBATCH*NPIX*CP];
static __device__ float g_Qb[NBATCH*NPIX*CP];
static __device__ float g_K[(size_t)NBATCH*NPIX*NPIX];    // raw Kb -> fused Keff (181 MB)

// ---------------- small setup kernels ----------------

// spatial gaussian table exp(-8*d2) for all (dy,dx) in [-40,40]^2
__global__ void k_eg() {
    int t = blockIdx.x*blockDim.x + threadIdx.x;
    if (t >= 81*81) return;
    int dy = t/81 - 40, dx = t%81 - 40;
    g_eg[t] = expf(-AG * (float)(dy*dy + dx*dx));
}

// gaussian kernel row sums via separability: sg_i = Sx*Sy - 1 (exclude self)
__global__ void k_rsg() {
    int i = blockIdx.x*blockDim.x + threadIdx.x;
    if (i >= NPIX) return;
    int y = i / WS, x = i % WS;
    float Sx = 0.f, Sy = 0.f;
    for (int j = 0; j < WS; j++) {
        int dx = x - j; Sx += expf(-AG * (float)(dx*dx));
        int dy = y - j; Sy += expf(-AG * (float)(dy*dy));
    }
    g_rsg[i] = rsqrtf(Sx*Sy - 1.0f);
}

// jax.image.resize(method='linear', antialias=True): triangle filter with
// kernel_scale = 321/41, per-output normalized weights. Fused 2D (separable
// normalized weights -> identical to jax's per-dim application).
__global__ void k_resize(const float* __restrict__ img) {
    int t = blockIdx.x*blockDim.x + threadIdx.x;
    if (t >= NBATCH*NPIX) return;
    int n = t / NPIX, p = t % NPIX;
    int oy = p / WS, ox = p % WS;

    float wy[18], wx[18];
    float sy = (oy + 0.5f)*INVSC - 0.5f;
    int jy0 = max(0, (int)ceilf(sy - INVSC));
    int jy1 = min(H_IN-1, (int)floorf(sy + INVSC));
    float sumy = 0.f;
    for (int j = jy0; j <= jy1; j++) {
        float w = fmaxf(1.0f - fabsf(sy - (float)j)*(1.0f/INVSC), 0.f);
        wy[j-jy0] = w; sumy += w;
    }
    float sx = (ox + 0.5f)*INVSC - 0.5f;
    int jx0 = max(0, (int)ceilf(sx - INVSC));
    int jx1 = min(W_IN-1, (int)floorf(sx + INVSC));
    float sumx = 0.f;
    for (int j = jx0; j <= jx1; j++) {
        float w = fmaxf(1.0f - fabsf(sx - (float)j)*(1.0f/INVSC), 0.f);
        wx[j-jx0] = w; sumx += w;
    }

    float a0 = 0.f, a1 = 0.f, a2 = 0.f;
    const float* b0 = img + (size_t)(n*3 + 0)*H_IN*W_IN;
    const float* b1 = img + (size_t)(n*3 + 1)*H_IN*W_IN;
    const float* b2 = img + (size_t)(n*3 + 2)*H_IN*W_IN;
    for (int jy = jy0; jy <= jy1; jy++) {
        float wyv = wy[jy-jy0];
        const float* r0 = b0 + (size_t)jy*W_IN;
        const float* r1 = b1 + (size_t)jy*W_IN;
        const float* r2 = b2 + (size_t)jy*W_IN;
        for (int jx = jx0; jx <= jx1; jx++) {
            float w = wyv * wx[jx-jx0];
            a0 = fmaf(w, r0[jx], a0);
            a1 = fmaf(w, r1[jx], a1);
            a2 = fmaf(w, r2[jx], a2);
        }
    }
    float inv = 1.0f/(sumy*sumx);
    float4 c; c.x = a0*inv; c.y = a1*inv; c.z = a2*inv; c.w = 0.f;
    ((float4*)g_colors)[t] = c;
}

// clamped softmax -> probs, logu, Q0
__global__ void k_probs(const float* __restrict__ pred) {
    int t = blockIdx.x*blockDim.x + threadIdx.x;
    if (t >= NBATCH*NPIX) return;
    int n = t / NPIX, p = t % NPIX;
    const float* base = pred + (size_t)n*NCH*NPIX + p;
    float x[NCH];
    float m = -1e30f;
    #pragma unroll
    for (int c = 0; c < NCH; c++) { x[c] = base[(size_t)c*NPIX]; m = fmaxf(m, x[c]); }
    float s = 0.f;
    #pragma unroll
    for (int c = 0; c < NCH; c++) { x[c] = __expf(x[c]-m); s += x[c]; }
    float inv = 1.0f/s;
    float s2 = 0.f;
    #pragma unroll
    for (int c = 0; c < NCH; c++) { x[c] = fminf(fmaxf(x[c]*inv, EPSV), 1.0f); s2 += x[c]; }
    float inv2 = 1.0f/s2;
    float* pp = g_probs + (size_t)t*CP;
    float* pl = g_logu  + (size_t)t*CP;
    float* pq = g_Qa    + (size_t)t*CP;
    #pragma unroll
    for (int c = 0; c < NCH; c++) {
        float v = x[c]*inv2;
        pp[c] = v; pl[c] = logf(v); pq[c] = v;
    }
    #pragma unroll
    for (int c = NCH; c < CP; c++) { pp[c] = 0.f; pl[c] = 0.f; pq[c] = 0.f; }
}

// raw bilateral kernel row + row sum (one block per (i,n))
__global__ void k_kbraw() {
    int i = blockIdx.x, n = blockIdx.y;
    int tid = threadIdx.x;
    int yi = i / WS, xi = i % WS;
    const float4* cols = ((const float4*)g_colors) + (size_t)n*NPIX;
    float4 ci = cols[i];
    float* Krow = g_K + ((size_t)(n*NPIX + i))*NPIX;
    float fyi = (float)yi, fxi = (float)xi;
    float sum = 0.f;
    for (int j = tid; j < NPIX; j += 256) {
        int yj = j / WS, xj = j % WS;
        float dy = fyi - (float)yj, dx = fxi - (float)xj;
        float4 cj = cols[j];
        float dr = ci.x - cj.x, dg = ci.y - cj.y, db = ci.z - cj.z;
        float d2 = fmaf(dy, dy, dx*dx);
        float cd2 = fmaf(dr, dr, fmaf(dg, dg, db*db));
        float v = __expf(fmaf(-ABF, d2, -BBF*cd2));
        if (j == i) v = 0.f;
        Krow[j] = v;
        sum += v;
    }
    // block reduce (256 threads)
    for (int o = 16; o; o >>= 1) sum += __shfl_down_sync(0xffffffffu, sum, o);
    __shared__ float red[8];
    int wid = tid >> 5, lane = tid & 31;
    if (lane == 0) red[wid] = sum;
    __syncthreads();
    if (wid == 0) {
        float v = (lane < 8) ? red[lane] : 0.f;
        for (int o = 4; o; o >>= 1) v += __shfl_down_sync(0xffffffffu, v, o);
        if (lane == 0) g_rsb[n*NPIX + i] = rsqrtf(v);
    }
}

// fuse: Keff = 10*Kb_norm + 3*Kg_norm (symmetric normalization), diag = 0
__global__ void k_combine() {
    int j = blockIdx.x*blockDim.x + threadIdx.x;
    if (j >= NPIX) return;
    int i = blockIdx.y, n = blockIdx.z;
    int yi = i / WS, xi = i % WS;
    int yj = j / WS, xj = j % WS;
    size_t idx = ((size_t)(n*NPIX + i))*NPIX + j;
    float v = CB * g_K[idx] * g_rsb[n*NPIX + i] * g_rsb[n*NPIX + j]
            + CG * g_eg[(yi - yj + 40)*81 + (xi - xj + 40)] * g_rsg[i] * g_rsg[j];
    if (j == i) v = 0.f;
    g_K[idx] = v;
}

// one mean-field iteration: msg = Keff @ Q, Qout = softmax_c(logu + msg)
// thread-per-row, Q chunked into smem (padded stride CP=24, warp-uniform LDS)
#define MSG_BLK 192
#define MSG_KC  768
__global__ void __launch_bounds__(MSG_BLK) k_msg(int dir) {
    extern __shared__ float Qs[];
    const float* Qin = dir ? g_Qb : g_Qa;
    float*       Qout = dir ? g_Qa : g_Qb;
    int n = blockIdx.y;
    int row = blockIdx.x*MSG_BLK + threadIdx.x;
    int rowc = min(row, NPIX-1);
    const float* __restrict__ Krow = g_K + ((size_t)(n*NPIX) + rowc)*NPIX;
    const float* __restrict__ Qn = Qin + (size_t)n*NPIX*CP;

    float acc[NCH];
    #pragma unroll
    for (int c = 0; c < NCH; c++) acc[c] = 0.f;

    for (int k0 = 0; k0 < NPIX; k0 += MSG_KC) {
        int kc = min(MSG_KC, NPIX - k0);
        int nv = (kc*CP) >> 2;
        const float4* src = (const float4*)(Qn + (size_t)k0*CP);
        for (int idx = threadIdx.x; idx < nv; idx += MSG_BLK)
            ((float4*)Qs)[idx] = src[idx];
        __syncthreads();
        const float* __restrict__ Kp = Krow + k0;
        #pragma unroll 4
        for (int k = 0; k < kc; k++) {
            float kv = __ldg(Kp + k);
            const float* q = Qs + k*CP;
            #pragma unroll
            for (int c = 0; c < NCH; c++) acc[c] = fmaf(kv, q[c], acc[c]);
        }
        __syncthreads();
    }

    if (row < NPIX) {
        const float* lg = g_logu + ((size_t)(n*NPIX + row))*CP;
        float lt[NCH];
        float m = -1e30f;
        #pragma unroll
        for (int c = 0; c < NCH; c++) { lt[c] = lg[c] + acc[c]; m = fmaxf(m, lt[c]); }
        float s = 0.f;
        #pragma unroll
        for (int c = 0; c < NCH; c++) { lt[c] = __expf(lt[c]-m); s += lt[c]; }
        float inv = 1.0f/s;
        float* o = Qout + ((size_t)(n*NPIX + row))*CP;
        #pragma unroll
        for (int c = 0; c < NCH; c++) o[c] = lt[c]*inv;
        o[21] = 0.f; o[22] = 0.f; o[23] = 0.f;
    }
}

// final: ps = renorm(max(Q, eps)); loss = mean_{n,pix} sum_c ps*log(clip(ps/probs,.05,20))
__global__ void k_loss(float* __restrict__ out) {
    int tid = threadIdx.x;
    float part = 0.f;
    for (int t = tid; t < NBATCH*NPIX; t += 1024) {
        const float* q  = g_Qa    + (size_t)t*CP;
        const float* pr = g_probs + (size_t)t*CP;
        float ps[NCH];
        float s = 0.f;
        #pragma unroll
        for (int c = 0; c < NCH; c++) { ps[c] = fmaxf(q[c], EPSV); s += ps[c]; }
        float inv = 1.0f/s;
        #pragma unroll
        for (int c = 0; c < NCH; c++) {
            float p = ps[c]*inv;
            float r = p/pr[c];
            r = fminf(fmaxf(r, 0.05f), 20.0f);
            part += p*logf(r);
        }
    }
    for (int o = 16; o; o >>= 1) part += __shfl_down_sync(0xffffffffu, part, o);
    __shared__ float red[32];
    int wid = tid >> 5, lane = tid & 31;
    if (lane == 0) red[wid] = part;
    __syncthreads();
    if (wid == 0) {
        float v = red[lane];
        for (int o = 16; o; o >>= 1) v += __shfl_down_sync(0xffffffffu, v, o);
        if (lane == 0) out[0] = v / (float)(NBATCH*NPIX);
    }
}

extern "C" void kernel_launch(void* const* d_in, const int* in_sizes, int n_in,
                              void* d_out, int out_size) {
    const float* images  = (const float*)d_in[0];
    const float* predict = (const float*)d_in[1];
    if (n_in >= 2 && in_sizes[0] < in_sizes[1]) {  // images is the larger input
        const float* tmp = images; images = predict; predict = tmp;
    }

    cudaFuncSetAttribute(k_msg, cudaFuncAttributeMaxDynamicSharedMemorySize,
                         MSG_KC*CP*(int)sizeof(float));

    k_eg<<<(81*81 + 255)/256, 256>>>();
    k_rsg<<<(NPIX + 255)/256, 256>>>();
    k_resize<<<(NBATCH*NPIX + 127)/128, 128>>>(images);
    k_probs<<<(NBATCH*NPIX + 127)/128, 128>>>(predict);
    k_kbraw<<<dim3(NPIX, NBATCH), 256>>>();
    k_combine<<<dim3((NPIX + 255)/256, NPIX, NBATCH), 256>>>();
    for (int it = 0; it < NITERS; it++) {
        k_msg<<<dim3((NPIX + MSG_BLK - 1)/MSG_BLK, NBATCH), MSG_BLK,
                MSG_KC*CP*sizeof(float)>>>(it & 1);
    }
    k_loss<<<1, 1024>>>((float*)d_out);
}

// round 3
// speedup vs baseline: 2.7844x; 2.7844x over previous
#include <cuda_runtime.h>
#include <math.h>

#define H_IN 321
#define W_IN 321
#define HS 41
#define WS 41
#define NPIX 1681
#define NCH 21
#define CP 24
#define NBATCH 16
#define NITERS 10

#define INVSC (321.0f/41.0f)
#define AG 8.0f                 /* 1/(2*(3/12)^2) */
#define ABF 0.011250f           /* 1/(2*(80/12)^2) */
#define BBF (1.0f/338.0f)       /* 1/(2*13^2) */
#define CG 3.0f
#define CB 10.0f
#define EPSV 1e-5f

#define KSPLIT 4
#define KSEG 421                /* ceil(1681/4) */
#define MB 128                  /* k_msg block / row tile */
#define KCH 128                 /* k chunk staged in smem */
#define NLB 64                  /* loss partial blocks */

// ---------------- static device buffers (no allocs allowed) ----------------
static __device__ float g_colors[NBATCH*NPIX*4];          // rgb + pad
static __device__ float g_rsg[NPIX];                      // 1/sqrt(row sum) gaussian
static __device__ float g_rsb[NBATCH*NPIX];               // 1/sqrt(row sum) bilateral
static __device__ float g_probs[NBATCH*NPIX*CP];
static __device__ float g_logu[NBATCH*NPIX*CP];
static __device__ float g_Qa[NBATCH*NPIX*CP];
static __device__ float g_Qb[NBATCH*NPIX*CP];
static __device__ float g_part[(size_t)KSPLIT*NBATCH*NPIX*CP]; // msg partials
static __device__ float g_lpart[NLB];
static __device__ float g_K[(size_t)NBATCH*NPIX*NPIX];    // fused Keff (181 MB), symmetric

// ---------------- setup kernels ----------------

__global__ void k_rsg() {
    int i = blockIdx.x*blockDim.x + threadIdx.x;
    if (i >= NPIX) return;
    int y = i / WS, x = i % WS;
    float Sx = 0.f, Sy = 0.f;
    for (int j = 0; j < WS; j++) {
        int dx = x - j; Sx += expf(-AG * (float)(dx*dx));
        int dy = y - j; Sy += expf(-AG * (float)(dy*dy));
    }
    g_rsg[i] = rsqrtf(Sx*Sy - 1.0f);
}

__global__ void k_resize(const float* __restrict__ img) {
    int t = blockIdx.x*blockDim.x + threadIdx.x;
    if (t >= NBATCH*NPIX) return;
    int n = t / NPIX, p = t % NPIX;
    int oy = p / WS, ox = p % WS;

    float wy[18], wx[18];
    float sy = (oy + 0.5f)*INVSC - 0.5f;
    int jy0 = max(0, (int)ceilf(sy - INVSC));
    int jy1 = min(H_IN-1, (int)floorf(sy + INVSC));
    float sumy = 0.f;
    for (int j = jy0; j <= jy1; j++) {
        float w = fmaxf(1.0f - fabsf(sy - (float)j)*(1.0f/INVSC), 0.f);
        wy[j-jy0] = w; sumy += w;
    }
    float sx = (ox + 0.5f)*INVSC - 0.5f;
    int jx0 = max(0, (int)ceilf(sx - INVSC));
    int jx1 = min(W_IN-1, (int)floorf(sx + INVSC));
    float sumx = 0.f;
    for (int j = jx0; j <= jx1; j++) {
        float w = fmaxf(1.0f - fabsf(sx - (float)j)*(1.0f/INVSC), 0.f);
        wx[j-jx0] = w; sumx += w;
    }

    float a0 = 0.f, a1 = 0.f, a2 = 0.f;
    const float* b0 = img + (size_t)(n*3 + 0)*H_IN*W_IN;
    const float* b1 = img + (size_t)(n*3 + 1)*H_IN*W_IN;
    const float* b2 = img + (size_t)(n*3 + 2)*H_IN*W_IN;
    for (int jy = jy0; jy <= jy1; jy++) {
        float wyv = wy[jy-jy0];
        const float* r0 = b0 + (size_t)jy*W_IN;
        const float* r1 = b1 + (size_t)jy*W_IN;
        const float* r2 = b2 + (size_t)jy*W_IN;
        for (int jx = jx0; jx <= jx1; jx++) {
            float w = wyv * wx[jx-jx0];
            a0 = fmaf(w, r0[jx], a0);
            a1 = fmaf(w, r1[jx], a1);
            a2 = fmaf(w, r2[jx], a2);
        }
    }
    float inv = 1.0f/(sumy*sumx);
    float4 c; c.x = a0*inv; c.y = a1*inv; c.z = a2*inv; c.w = 0.f;
    ((float4*)g_colors)[t] = c;
}

__global__ void k_probs(const float* __restrict__ pred) {
    int t = blockIdx.x*blockDim.x + threadIdx.x;
    if (t >= NBATCH*NPIX) return;
    int n = t / NPIX, p = t % NPIX;
    const float* base = pred + (size_t)n*NCH*NPIX + p;
    float x[NCH];
    float m = -1e30f;
    #pragma unroll
    for (int c = 0; c < NCH; c++) { x[c] = base[(size_t)c*NPIX]; m = fmaxf(m, x[c]); }
    float s = 0.f;
    #pragma unroll
    for (int c = 0; c < NCH; c++) { x[c] = __expf(x[c]-m); s += x[c]; }
    float inv = 1.0f/s;
    float s2 = 0.f;
    #pragma unroll
    for (int c = 0; c < NCH; c++) { x[c] = fminf(fmaxf(x[c]*inv, EPSV), 1.0f); s2 += x[c]; }
    float inv2 = 1.0f/s2;
    float* pp = g_probs + (size_t)t*CP;
    float* pl = g_logu  + (size_t)t*CP;
    float* pq = g_Qa    + (size_t)t*CP;
    #pragma unroll
    for (int c = 0; c < NCH; c++) {
        float v = x[c]*inv2;
        pp[c] = v; pl[c] = logf(v); pq[c] = v;
    }
    #pragma unroll
    for (int c = NCH; c < CP; c++) { pp[c] = 0.f; pl[c] = 0.f; pq[c] = 0.f; }
}

// bilateral row sums only (no K store; exp recomputed in k_keff)
__global__ void k_sums() {
    int i = blockIdx.x, n = blockIdx.y;
    int tid = threadIdx.x;
    int yi = i / WS, xi = i % WS;
    const float4* cols = ((const float4*)g_colors) + (size_t)n*NPIX;
    float4 ci = cols[i];
    float fyi = (float)yi, fxi = (float)xi;
    float sum = 0.f;
    for (int j = tid; j < NPIX; j += 256) {
        int yj = j / WS, xj = j % WS;
        float dy = fyi - (float)yj, dx = fxi - (float)xj;
        float4 cj = cols[j];
        float dr = ci.x - cj.x, dg = ci.y - cj.y, db = ci.z - cj.z;
        float d2 = fmaf(dy, dy, dx*dx);
        float cd2 = fmaf(dr, dr, fmaf(dg, dg, db*db));
        float v = __expf(fmaf(-ABF, d2, -BBF*cd2));
        if (j == i) v = 0.f;
        sum += v;
    }
    for (int o = 16; o; o >>= 1) sum += __shfl_down_sync(0xffffffffu, sum, o);
    __shared__ float red[8];
    int wid = tid >> 5, lane = tid & 31;
    if (lane == 0) red[wid] = sum;
    __syncthreads();
    if (wid == 0) {
        float v = (lane < 8) ? red[lane] : 0.f;
        for (int o = 4; o; o >>= 1) v += __shfl_down_sync(0xffffffffu, v, o);
        if (lane == 0) g_rsb[n*NPIX + i] = rsqrtf(v);
    }
}

// single fused write of Keff = 10*Kb_norm + 3*Kg_norm, diag 0 (symmetric)
__global__ void k_keff() {
    int j = blockIdx.x*blockDim.x + threadIdx.x;
    if (j >= NPIX) return;
    int i = blockIdx.y, n = blockIdx.z;
    int yi = i / WS, xi = i % WS;
    int yj = j / WS, xj = j % WS;
    const float4* cols = ((const float4*)g_colors) + (size_t)n*NPIX;
    float4 ci = cols[i];
    float4 cj = cols[j];
    float dy = (float)(yi - yj), dx = (float)(xi - xj);
    float dr = ci.x - cj.x, dg = ci.y - cj.y, db = ci.z - cj.z;
    float d2 = fmaf(dy, dy, dx*dx);
    float cd2 = fmaf(dr, dr, fmaf(dg, dg, db*db));
    float kb = __expf(fmaf(-ABF, d2, -BBF*cd2)) * g_rsb[n*NPIX + i] * g_rsb[n*NPIX + j];
    float kg = __expf(-AG * d2) * g_rsg[i] * g_rsg[j];
    float v = CB * kb + CG * kg;
    if (j == i) v = 0.f;
    g_K[((size_t)(n*NPIX + i))*NPIX + j] = v;
}

// ---------------- mean-field iteration ----------------
// part[kz][n][row][c] = sum_{k in seg kz} K[k][row] * Q[k][c]
// K symmetric -> column read == row read; warp reads contiguous 128B per k.
// blockIdx.y = kz (k-split for occupancy), packed f32x2 FMA (12 per k).
__global__ void __launch_bounds__(MB) k_msg(int dir) {
    __shared__ float Qs[KCH*CP];
    const float* Qin = dir ? g_Qb : g_Qa;
    int n = blockIdx.z;
    int kz = blockIdx.y;
    int row = blockIdx.x*MB + threadIdx.x;
    int rowc = min(row, NPIX-1);
    int kbase = kz*KSEG;
    int kend = min(NPIX, kbase + KSEG);
    const float* __restrict__ Qn = Qin + (size_t)n*NPIX*CP;
    const float* __restrict__ Kn = g_K + (size_t)n*NPIX*NPIX;

    unsigned long long acc[12];
    #pragma unroll
    for (int j = 0; j < 12; j++) acc[j] = 0ull;

    for (int k0 = kbase; k0 < kend; k0 += KCH) {
        int kc = min(KCH, kend - k0);
        int nv = kc*6;  // float4 count (CP=24 -> 6 per k)
        const float4* src = (const float4*)(Qn + (size_t)k0*CP);
        for (int idx = threadIdx.x; idx < nv; idx += MB)
            ((float4*)Qs)[idx] = src[idx];
        __syncthreads();
        const float* __restrict__ Kp = Kn + (size_t)k0*NPIX + rowc;
        #pragma unroll 4
        for (int kk = 0; kk < kc; kk++) {
            float kv = __ldg(Kp + (size_t)kk*NPIX);
            unsigned long long kv2;
            unsigned int kvb = __float_as_uint(kv);
            asm("mov.b64 %0, {%1, %1};" : "=l"(kv2) : "r"(kvb));
            const ulonglong2* q = (const ulonglong2*)(Qs + kk*CP);
            #pragma unroll
            for (int j = 0; j < 6; j++) {
                ulonglong2 v = q[j];
                asm("fma.rn.f32x2 %0, %1, %2, %0;" : "+l"(acc[2*j])   : "l"(kv2), "l"(v.x));
                asm("fma.rn.f32x2 %0, %1, %2, %0;" : "+l"(acc[2*j+1]) : "l"(kv2), "l"(v.y));
            }
        }
        __syncthreads();
    }

    if (row < NPIX) {
        unsigned long long* o = (unsigned long long*)
            (g_part + (((size_t)kz*NBATCH + n)*NPIX + row)*CP);
        #pragma unroll
        for (int j = 0; j < 12; j++) o[j] = acc[j];
    }
}

// combine partials + softmax with logu
__global__ void k_update(int dir) {
    int t = blockIdx.x*blockDim.x + threadIdx.x;
    if (t >= NBATCH*NPIX) return;
    float* Qout = dir ? g_Qa : g_Qb;
    const float* lg = g_logu + (size_t)t*CP;
    const float* p0 = g_part + (size_t)t*CP;
    const float* p1 = p0 + (size_t)NBATCH*NPIX*CP;
    const float* p2 = p1 + (size_t)NBATCH*NPIX*CP;
    const float* p3 = p2 + (size_t)NBATCH*NPIX*CP;
    float lt[NCH];
    float m = -1e30f;
    #pragma unroll
    for (int c = 0; c < NCH; c++) {
        lt[c] = lg[c] + ((p0[c] + p1[c]) + (p2[c] + p3[c]));
        m = fmaxf(m, lt[c]);
    }
    float s = 0.f;
    #pragma unroll
    for (int c = 0; c < NCH; c++) { lt[c] = __expf(lt[c]-m); s += lt[c]; }
    float inv = 1.0f/s;
    float* o = Qout + (size_t)t*CP;
    #pragma unroll
    for (int c = 0; c < NCH; c++) o[c] = lt[c]*inv;
    o[21] = 0.f; o[22] = 0.f; o[23] = 0.f;
}

// ---------------- loss: 2-stage reduction ----------------
__global__ void k_loss1() {
    int tid = threadIdx.x;
    float part = 0.f;
    for (int t = blockIdx.x*256 + tid; t < NBATCH*NPIX; t += NLB*256) {
        const float* q  = g_Qa    + (size_t)t*CP;
        const float* pr = g_probs + (size_t)t*CP;
        float ps[NCH];
        float s = 0.f;
        #pragma unroll
        for (int c = 0; c < NCH; c++) { ps[c] = fmaxf(q[c], EPSV); s += ps[c]; }
        float inv = 1.0f/s;
        #pragma unroll
        for (int c = 0; c < NCH; c++) {
            float p = ps[c]*inv;
            float r = p/pr[c];
            r = fminf(fmaxf(r, 0.05f), 20.0f);
            part += p*logf(r);
        }
    }
    for (int o = 16; o; o >>= 1) part += __shfl_down_sync(0xffffffffu, part, o);
    __shared__ float red[8];
    int wid = tid >> 5, lane = tid & 31;
    if (lane == 0) red[wid] = part;
    __syncthreads();
    if (wid == 0) {
        float v = (lane < 8) ? red[lane] : 0.f;
        for (int o = 4; o; o >>= 1) v += __shfl_down_sync(0xffffffffu, v, o);
        if (lane == 0) g_lpart[blockIdx.x] = v;
    }
}

__global__ void k_loss2(float* __restrict__ out) {
    int lane = threadIdx.x;   // 64 threads = 2 warps
    float v = g_lpart[lane];
    for (int o = 16; o; o >>= 1) v += __shfl_down_sync(0xffffffffu, v, o);
    __shared__ float red[2];
    if ((lane & 31) == 0) red[lane >> 5] = v;
    __syncthreads();
    if (lane == 0) out[0] = (red[0] + red[1]) / (float)(NBATCH*NPIX);
}

extern "C" void kernel_launch(void* const* d_in, const int* in_sizes, int n_in,
                              void* d_out, int out_size) {
    const float* images  = (const float*)d_in[0];
    const float* predict = (const float*)d_in[1];
    if (n_in >= 2 && in_sizes[0] < in_sizes[1]) {
        const float* tmp = images; images = predict; predict = tmp;
    }

    k_rsg<<<(NPIX + 255)/256, 256>>>();
    k_resize<<<(NBATCH*NPIX + 127)/128, 128>>>(images);
    k_probs<<<(NBATCH*NPIX + 127)/128, 128>>>(predict);
    k_sums<<<dim3(NPIX, NBATCH), 256>>>();
    k_keff<<<dim3((NPIX + 255)/256, NPIX, NBATCH), 256>>>();
    for (int it = 0; it < NITERS; it++) {
        int dir = it & 1;
        k_msg<<<dim3((NPIX + MB - 1)/MB, KSPLIT, NBATCH), MB>>>(dir);
        k_update<<<(NBATCH*NPIX + 127)/128, 128>>>(dir);
    }
    k_loss1<<<NLB, 256>>>();
    k_loss2<<<1, 64>>>((float*)d_out);
}

// round 4
// speedup vs baseline: 3.3604x; 1.2069x over previous
#include <cuda_runtime.h>
#include <math.h>

#define H_IN 321
#define W_IN 321
#define HS 41
#define WS 41
#define NPIX 1681
#define NCH 21
#define CP 24
#define NBATCH 16
#define NITERS 10

#define INVSC (321.0f/41.0f)
#define AG 8.0f                 /* 1/(2*(3/12)^2) */
#define ABF 0.011250f           /* 1/(2*(80/12)^2) */
#define BBF (1.0f/338.0f)       /* 1/(2*13^2) */
#define CG 3.0f
#define CB 10.0f
#define EPSV 1e-5f

#define KSTRIDE 1684            /* padded K row stride (mult of 4) */
#define KSPLIT 4
#define KSEG 421                /* ceil(1681/4) */
#define TILE_M 128
#define KCH2 32
#define NLB 64

// exact for 0 <= j < 2000: y = j/41
__device__ __forceinline__ int div41(int j) { return (j*51151) >> 21; }

// ---------------- static device buffers ----------------
static __device__ float  g_colors[NBATCH*NPIX*4];
static __device__ float2 g_pos[NPIX];
static __device__ float  g_rsg[NPIX];
static __device__ float  g_rsb[NBATCH*NPIX];
static __device__ float  g_probs[NBATCH*NPIX*CP];
static __device__ float  g_logu[NBATCH*NPIX*CP];
static __device__ float  g_Qa[NBATCH*NPIX*CP];
static __device__ float  g_Qb[NBATCH*NPIX*CP];
static __device__ float  g_part[(size_t)KSPLIT*NBATCH*NPIX*CP];
static __device__ float  g_lpart[NLB];
static __device__ float  g_K[(size_t)NBATCH*NPIX*KSTRIDE + 256];

// ---------------- setup ----------------

__global__ void k_rsg() {
    int i = blockIdx.x*blockDim.x + threadIdx.x;
    if (i >= NPIX) return;
    int y = div41(i), x = i - y*41;
    g_pos[i] = make_float2((float)x, (float)y);
    float Sx = 0.f, Sy = 0.f;
    for (int j = 0; j < WS; j++) {
        int dx = x - j; Sx += expf(-AG * (float)(dx*dx));
        int dy = y - j; Sy += expf(-AG * (float)(dy*dy));
    }
    g_rsg[i] = rsqrtf(Sx*Sy - 1.0f);
}

__global__ void k_resize(const float* __restrict__ img) {
    int t = blockIdx.x*blockDim.x + threadIdx.x;
    if (t >= NBATCH*NPIX) return;
    int n = t / NPIX, p = t - n*NPIX;
    int oy = div41(p), ox = p - oy*41;

    float wy[18], wx[18];
    float sy = (oy + 0.5f)*INVSC - 0.5f;
    int jy0 = max(0, (int)ceilf(sy - INVSC));
    int jy1 = min(H_IN-1, (int)floorf(sy + INVSC));
    float sumy = 0.f;
    for (int j = jy0; j <= jy1; j++) {
        float w = fmaxf(1.0f - fabsf(sy - (float)j)*(1.0f/INVSC), 0.f);
        wy[j-jy0] = w; sumy += w;
    }
    float sx = (ox + 0.5f)*INVSC - 0.5f;
    int jx0 = max(0, (int)ceilf(sx - INVSC));
    int jx1 = min(W_IN-1, (int)floorf(sx + INVSC));
    float sumx = 0.f;
    for (int j = jx0; j <= jx1; j++) {
        float w = fmaxf(1.0f - fabsf(sx - (float)j)*(1.0f/INVSC), 0.f);
        wx[j-jx0] = w; sumx += w;
    }

    float a0 = 0.f, a1 = 0.f, a2 = 0.f;
    const float* b0 = img + (size_t)(n*3 + 0)*H_IN*W_IN;
    const float* b1 = img + (size_t)(n*3 + 1)*H_IN*W_IN;
    const float* b2 = img + (size_t)(n*3 + 2)*H_IN*W_IN;
    for (int jy = jy0; jy <= jy1; jy++) {
        float wyv = wy[jy-jy0];
        const float* r0 = b0 + (size_t)jy*W_IN;
        const float* r1 = b1 + (size_t)jy*W_IN;
        const float* r2 = b2 + (size_t)jy*W_IN;
        for (int jx = jx0; jx <= jx1; jx++) {
            float w = wyv * wx[jx-jx0];
            a0 = fmaf(w, r0[jx], a0);
            a1 = fmaf(w, r1[jx], a1);
            a2 = fmaf(w, r2[jx], a2);
        }
    }
    float inv = 1.0f/(sumy*sumx);
    float4 c; c.x = a0*inv; c.y = a1*inv; c.z = a2*inv; c.w = 0.f;
    ((float4*)g_colors)[t] = c;
}

__global__ void k_probs(const float* __restrict__ pred) {
    int t = blockIdx.x*blockDim.x + threadIdx.x;
    if (t >= NBATCH*NPIX) return;
    int n = t / NPIX, p = t - n*NPIX;
    const float* base = pred + (size_t)n*NCH*NPIX + p;
    float x[NCH];
    float m = -1e30f;
    #pragma unroll
    for (int c = 0; c < NCH; c++) { x[c] = base[(size_t)c*NPIX]; m = fmaxf(m, x[c]); }
    float s = 0.f;
    #pragma unroll
    for (int c = 0; c < NCH; c++) { x[c] = __expf(x[c]-m); s += x[c]; }
    float inv = 1.0f/s;
    float s2 = 0.f;
    #pragma unroll
    for (int c = 0; c < NCH; c++) { x[c] = fminf(fmaxf(x[c]*inv, EPSV), 1.0f); s2 += x[c]; }
    float inv2 = 1.0f/s2;
    float* pp = g_probs + (size_t)t*CP;
    float* pl = g_logu  + (size_t)t*CP;
    float* pq = g_Qa    + (size_t)t*CP;
    #pragma unroll
    for (int c = 0; c < NCH; c++) {
        float v = x[c]*inv2;
        pp[c] = v; pl[c] = __logf(v); pq[c] = v;
    }
    #pragma unroll
    for (int c = NCH; c < CP; c++) { pp[c] = 0.f; pl[c] = 0.f; pq[c] = 0.f; }
}

// bilateral row sums (self term included -> subtract 1)
__global__ void k_sums() {
    int i = blockIdx.x, n = blockIdx.y;
    int tid = threadIdx.x;
    const float4* cols = ((const float4*)g_colors) + (size_t)n*NPIX;
    float4 ci = cols[i];
    float2 pi = g_pos[i];
    float sum = 0.f;
    for (int j = tid; j < NPIX; j += 256) {
        float2 pj = g_pos[j];
        float4 cj = cols[j];
        float dy = pi.y - pj.y, dx = pi.x - pj.x;
        float dr = ci.x - cj.x, dg = ci.y - cj.y, db = ci.z - cj.z;
        float d2 = fmaf(dy, dy, dx*dx);
        float cd2 = fmaf(dr, dr, fmaf(dg, dg, db*db));
        sum += __expf(fmaf(-ABF, d2, -BBF*cd2));
    }
    for (int o = 16; o; o >>= 1) sum += __shfl_down_sync(0xffffffffu, sum, o);
    __shared__ float red[8];
    int wid = tid >> 5, lane = tid & 31;
    if (lane == 0) red[wid] = sum;
    __syncthreads();
    if (wid == 0) {
        float v = (lane < 8) ? red[lane] : 0.f;
        for (int o = 4; o; o >>= 1) v += __shfl_down_sync(0xffffffffu, v, o);
        if (lane == 0) g_rsb[n*NPIX + i] = rsqrtf(v - 1.0f);
    }
}

// fused Keff = 10*Kb_norm + 3*Kg_norm, diag 0 (symmetric), padded stride
__global__ void k_keff() {
    int j = blockIdx.x*blockDim.x + threadIdx.x;
    if (j >= NPIX) return;
    int i = blockIdx.y, n = blockIdx.z;
    const float4* cols = ((const float4*)g_colors) + (size_t)n*NPIX;
    float4 ci = cols[i];
    float4 cj = cols[j];
    float2 pi = g_pos[i];
    float2 pj = g_pos[j];
    float dy = pi.y - pj.y, dx = pi.x - pj.x;
    float dr = ci.x - cj.x, dg = ci.y - cj.y, db = ci.z - cj.z;
    float d2 = fmaf(dy, dy, dx*dx);
    float cd2 = fmaf(dr, dr, fmaf(dg, dg, db*db));
    float kb = __expf(fmaf(-ABF, d2, -BBF*cd2)) * g_rsb[n*NPIX + i] * g_rsb[n*NPIX + j];
    float kg = __expf(-AG * d2) * g_rsg[i] * g_rsg[j];
    float v = fmaf(CB, kb, CG*kg);
    if (j == i) v = 0.f;
    g_K[((size_t)(n*NPIX + i))*KSTRIDE + j] = v;
}

// ---------------- mean-field: register-tiled msg GEMM ----------------
// part[kz][n][row][c] = sum_{k in seg} K[k][row] * Q[k][c]   (K symmetric)
// thread tile: 4 rows x 6 channels (packed f32x2); block tile 128 rows.
__global__ void __launch_bounds__(128) k_msg(int dir) {
    __shared__ float Kt[KCH2][TILE_M];   // 16 KB
    __shared__ float Qt[KCH2][CP];       // 3 KB
    const float* Qin = dir ? g_Qb : g_Qa;
    int n = blockIdx.z, kz = blockIdx.y;
    int rowbase = blockIdx.x * TILE_M;
    int tid = threadIdx.x;
    int ng = tid & 3, mg = tid >> 2;     // ng: channel group (6 ch), mg: 4-row group
    int kbase = kz*KSEG, kend = min(NPIX, kbase + KSEG);
    const float* __restrict__ Qn = Qin + (size_t)n*NPIX*CP;
    const float* __restrict__ Kn = g_K + (size_t)n*NPIX*KSTRIDE;

    unsigned long long a00=0,a01=0,a02=0, a10=0,a11=0,a12=0,
                       a20=0,a21=0,a22=0, a30=0,a31=0,a32=0;

    for (int k0 = kbase; k0 < kend; k0 += KCH2) {
        int kc = min(KCH2, kend - k0);
        // stage K tile (coalesced float4; row overread lands in padded/valid mem)
        for (int idx = tid; idx < kc*(TILE_M/4); idx += 128) {
            int kk = idx >> 5, r4 = idx & 31;
            *(float4*)&Kt[kk][r4*4] =
                *(const float4*)(Kn + (size_t)(k0+kk)*KSTRIDE + rowbase + r4*4);
        }
        // stage Q tile (contiguous copy)
        for (int idx = tid; idx < kc*6; idx += 128)
            ((float4*)Qt)[idx] = *((const float4*)(Qn + (size_t)k0*CP) + idx);
        __syncthreads();
        #pragma unroll 4
        for (int kk = 0; kk < kc; kk++) {
            float4 kv = *(const float4*)&Kt[kk][mg*4];
            const float* qb = &Qt[kk][ng*6];
            unsigned long long q0 = *(const unsigned long long*)(qb);
            unsigned long long q1 = *(const unsigned long long*)(qb+2);
            unsigned long long q2 = *(const unsigned long long*)(qb+4);
            unsigned long long k0d,k1d,k2d,k3d;
            unsigned int b0=__float_as_uint(kv.x), b1=__float_as_uint(kv.y);
            unsigned int b2=__float_as_uint(kv.z), b3=__float_as_uint(kv.w);
            asm("mov.b64 %0, {%1,%1};" : "=l"(k0d) : "r"(b0));
            asm("mov.b64 %0, {%1,%1};" : "=l"(k1d) : "r"(b1));
            asm("mov.b64 %0, {%1,%1};" : "=l"(k2d) : "r"(b2));
            asm("mov.b64 %0, {%1,%1};" : "=l"(k3d) : "r"(b3));
            asm("fma.rn.f32x2 %0, %1, %2, %0;" : "+l"(a00) : "l"(k0d), "l"(q0));
            asm("fma.rn.f32x2 %0, %1, %2, %0;" : "+l"(a01) : "l"(k0d), "l"(q1));
            asm("fma.rn.f32x2 %0, %1, %2, %0;" : "+l"(a02) : "l"(k0d), "l"(q2));
            asm("fma.rn.f32x2 %0, %1, %2, %0;" : "+l"(a10) : "l"(k1d), "l"(q0));
            asm("fma.rn.f32x2 %0, %1, %2, %0;" : "+l"(a11) : "l"(k1d), "l"(q1));
            asm("fma.rn.f32x2 %0, %1, %2, %0;" : "+l"(a12) : "l"(k1d), "l"(q2));
            asm("fma.rn.f32x2 %0, %1, %2, %0;" : "+l"(a20) : "l"(k2d), "l"(q0));
            asm("fma.rn.f32x2 %0, %1, %2, %0;" : "+l"(a21) : "l"(k2d), "l"(q1));
            asm("fma.rn.f32x2 %0, %1, %2, %0;" : "+l"(a22) : "l"(k2d), "l"(q2));
            asm("fma.rn.f32x2 %0, %1, %2, %0;" : "+l"(a30) : "l"(k3d), "l"(q0));
            asm("fma.rn.f32x2 %0, %1, %2, %0;" : "+l"(a31) : "l"(k3d), "l"(q1));
            asm("fma.rn.f32x2 %0, %1, %2, %0;" : "+l"(a32) : "l"(k3d), "l"(q2));
        }
        __syncthreads();
    }

    float* pb = g_part + (((size_t)kz*NBATCH + n)*NPIX)*CP;
    int r0 = rowbase + mg*4;
    unsigned long long* o;
    if (r0 + 0 < NPIX) { o = (unsigned long long*)(pb + (size_t)(r0+0)*CP + ng*6); o[0]=a00; o[1]=a01; o[2]=a02; }
    if (r0 + 1 < NPIX) { o = (unsigned long long*)(pb + (size_t)(r0+1)*CP + ng*6); o[0]=a10; o[1]=a11; o[2]=a12; }
    if (r0 + 2 < NPIX) { o = (unsigned long long*)(pb + (size_t)(r0+2)*CP + ng*6); o[0]=a20; o[1]=a21; o[2]=a22; }
    if (r0 + 3 < NPIX) { o = (unsigned long long*)(pb + (size_t)(r0+3)*CP + ng*6); o[0]=a30; o[1]=a31; o[2]=a32; }
}

// combine partials + softmax with logu
__global__ void k_update(int dir) {
    int t = blockIdx.x*blockDim.x + threadIdx.x;
    if (t >= NBATCH*NPIX) return;
    float* Qout = dir ? g_Qa : g_Qb;
    const float* lg = g_logu + (size_t)t*CP;
    const float* p0 = g_part + (size_t)t*CP;
    const float* p1 = p0 + (size_t)NBATCH*NPIX*CP;
    const float* p2 = p1 + (size_t)NBATCH*NPIX*CP;
    const float* p3 = p2 + (size_t)NBATCH*NPIX*CP;
    float lt[NCH];
    float m = -1e30f;
    #pragma unroll
    for (int c = 0; c < NCH; c++) {
        lt[c] = lg[c] + ((p0[c] + p1[c]) + (p2[c] + p3[c]));
        m = fmaxf(m, lt[c]);
    }
    float s = 0.f;
    #pragma unroll
    for (int c = 0; c < NCH; c++) { lt[c] = __expf(lt[c]-m); s += lt[c]; }
    float inv = 1.0f/s;
    float* o = Qout + (size_t)t*CP;
    #pragma unroll
    for (int c = 0; c < NCH; c++) o[c] = lt[c]*inv;
    o[21] = 0.f; o[22] = 0.f; o[23] = 0.f;
}

// ---------------- loss ----------------
__global__ void k_loss1() {
    int tid = threadIdx.x;
    float part = 0.f;
    for (int t = blockIdx.x*256 + tid; t < NBATCH*NPIX; t += NLB*256) {
        const float* q  = g_Qa    + (size_t)t*CP;
        const float* pr = g_probs + (size_t)t*CP;
        float ps[NCH];
        float s = 0.f;
        #pragma unroll
        for (int c = 0; c < NCH; c++) { ps[c] = fmaxf(q[c], EPSV); s += ps[c]; }
        float inv = 1.0f/s;
        #pragma unroll
        for (int c = 0; c < NCH; c++) {
            float p = ps[c]*inv;
            float r = p/pr[c];
            r = fminf(fmaxf(r, 0.05f), 20.0f);
            part += p*__logf(r);
        }
    }
    for (int o = 16; o; o >>= 1) part += __shfl_down_sync(0xffffffffu, part, o);
    __shared__ float red[8];
    int wid = tid >> 5, lane = tid & 31;
    if (lane == 0) red[wid] = part;
    __syncthreads();
    if (wid == 0) {
        float v = (lane < 8) ? red[lane] : 0.f;
        for (int o = 4; o; o >>= 1) v += __shfl_down_sync(0xffffffffu, v, o);
        if (lane == 0) g_lpart[blockIdx.x] = v;
    }
}

__global__ void k_loss2(float* __restrict__ out) {
    int lane = threadIdx.x;   // 64 threads
    float v = g_lpart[lane];
    for (int o = 16; o; o >>= 1) v += __shfl_down_sync(0xffffffffu, v, o);
    __shared__ float red[2];
    if ((lane & 31) == 0) red[lane >> 5] = v;
    __syncthreads();
    if (lane == 0) out[0] = (red[0] + red[1]) / (float)(NBATCH*NPIX);
}

extern "C" void kernel_launch(void* const* d_in, const int* in_sizes, int n_in,
                              void* d_out, int out_size) {
    const float* images  = (const float*)d_in[0];
    const float* predict = (const float*)d_in[1];
    if (n_in >= 2 && in_sizes[0] < in_sizes[1]) {
        const float* tmp = images; images = predict; predict = tmp;
    }

    k_rsg<<<(NPIX + 255)/256, 256>>>();
    k_resize<<<(NBATCH*NPIX + 127)/128, 128>>>(images);
    k_probs<<<(NBATCH*NPIX + 127)/128, 128>>>(predict);
    k_sums<<<dim3(NPIX, NBATCH), 256>>>();
    k_keff<<<dim3((NPIX + 255)/256, NPIX, NBATCH), 256>>>();
    for (int it = 0; it < NITERS; it++) {
        int dir = it & 1;
        k_msg<<<dim3((NPIX + TILE_M - 1)/TILE_M, KSPLIT, NBATCH), 128>>>(dir);
        k_update<<<(NBATCH*NPIX + 127)/128, 128>>>(dir);
    }
    k_loss1<<<NLB, 256>>>();
    k_loss2<<<1, 64>>>((float*)d_out);
}